// round 6
// baseline (speedup 1.0000x reference)
#include <cuda_runtime.h>
#include <cuda_fp16.h>
#include <cstdint>
#include <cstddef>
#include <cstring>

#define N_NODES 8192
#define D 128
#define KC 128                       // K per stage (two 64-k sub-tiles)
#define NITER (N_NODES / KC)         // 64
#define MT 32                        // M rows per CTA
#define A_SUB_BYTES (MT * 64 * 2)        // 4096
#define B_SUB_BYTES (64 * D * 2)         // 16384
#define STAGE_BYTES (2 * A_SUB_BYTES + 2 * B_SUB_BYTES)   // 40960
#define SMEM_BYTES (2 * STAGE_BYTES)                      // 81920

// ---------------- device scratch ----------------
__device__ float g_dinv[N_NODES];
__device__ __half g_h[(size_t)N_NODES * D];   // dinv-scaled projected features, fp16 [k][n]

// ---------------- helpers ----------------
__device__ __forceinline__ uint32_t smem_u32(const void* p) {
    uint32_t a;
    asm("{ .reg .u64 t; cvta.to.shared.u64 t, %1; cvt.u32.u64 %0, t; }" : "=r"(a) : "l"(p));
    return a;
}
__device__ __forceinline__ void cp_async16(uint32_t dst, const void* src) {
    asm volatile("cp.async.cg.shared.global [%0], [%1], 16;" :: "r"(dst), "l"(src));
}
__device__ __forceinline__ void cp_commit() {
    asm volatile("cp.async.commit_group;" ::: "memory");
}
__device__ __forceinline__ void cp_wait0() {
    asm volatile("cp.async.wait_group 0;" ::: "memory");
}
__device__ __forceinline__ void ldsm_x4(uint32_t* r, uint32_t a) {
    asm volatile("ldmatrix.sync.aligned.m8n8.x4.shared.b16 {%0,%1,%2,%3}, [%4];"
                 : "=r"(r[0]), "=r"(r[1]), "=r"(r[2]), "=r"(r[3]) : "r"(a));
}
__device__ __forceinline__ void ldsm_x4_t(uint32_t* r, uint32_t a) {
    asm volatile("ldmatrix.sync.aligned.m8n8.x4.trans.shared.b16 {%0,%1,%2,%3}, [%4];"
                 : "=r"(r[0]), "=r"(r[1]), "=r"(r[2]), "=r"(r[3]) : "r"(a));
}
__device__ __forceinline__ void mma16816(float* c, const uint32_t* a, uint32_t b0, uint32_t b1) {
    asm volatile(
        "mma.sync.aligned.m16n8k16.row.col.f32.f16.f16.f32 "
        "{%0,%1,%2,%3},{%4,%5,%6,%7},{%8,%9},{%0,%1,%2,%3};"
        : "+f"(c[0]), "+f"(c[1]), "+f"(c[2]), "+f"(c[3])
        : "r"(a[0]), "r"(a[1]), "r"(a[2]), "r"(a[3]), "r"(b0), "r"(b1));
}
__device__ __forceinline__ void sts128(uint32_t addr, uint4 v) {
    asm volatile("st.shared.v4.u32 [%0], {%1,%2,%3,%4};"
                 :: "r"(addr), "r"(v.x), "r"(v.y), "r"(v.z), "r"(v.w));
}
__device__ __forceinline__ uint32_t h2u(__half2 h) {
    uint32_t u; __builtin_memcpy(&u, &h, 4); return u;
}

// ---------------------------------------------------------------------------
// Kernel 0: rowsum -> dinv  (41us @ 83-84% DRAM — near roofline, unchanged)
// ---------------------------------------------------------------------------
__global__ void __launch_bounds__(256) rowsum_kernel(const float* __restrict__ adj) {
    int row = blockIdx.x;
    const float4* p = reinterpret_cast<const float4*>(adj + (size_t)row * N_NODES);
    float s = 0.f;
    #pragma unroll 8
    for (int i = threadIdx.x; i < N_NODES / 4; i += 256) {
        float4 v = p[i];
        s += (v.x + v.y) + (v.z + v.w);
    }
    #pragma unroll
    for (int o = 16; o > 0; o >>= 1) s += __shfl_down_sync(0xffffffffu, s, o);
    __shared__ float red[8];
    int lane = threadIdx.x & 31, wid = threadIdx.x >> 5;
    if (lane == 0) red[wid] = s;
    __syncthreads();
    if (wid == 0) {
        s = (lane < 8) ? red[lane] : 0.f;
        #pragma unroll
        for (int o = 4; o > 0; o >>= 1) s += __shfl_down_sync(0xffffffffu, s, o);
        if (lane == 0) g_dinv[row] = (s > 0.f) ? rsqrtf(s) : 0.f;
    }
}

// ---------------------------------------------------------------------------
// Kernel 1: g_h[k][n] = fp16( dinv[k] * (x[k,:] @ W)[n] )
// ---------------------------------------------------------------------------
__global__ void __launch_bounds__(256) proj_kernel(const float* __restrict__ x,
                                                   const float* __restrict__ w) {
    __shared__ float xs[32][D];
    int row0 = blockIdx.x * 32;
    int tid = threadIdx.x;
    for (int i = tid; i < 32 * D; i += 256)
        xs[i / D][i % D] = x[(size_t)(row0 + i / D) * D + (i % D)];
    __syncthreads();

    int d = tid & 127;
    int half_ = tid >> 7;
    float acc[16];
    #pragma unroll
    for (int r = 0; r < 16; r++) acc[r] = 0.f;

    for (int k = 0; k < D; k++) {
        float wv = w[k * D + d];
        #pragma unroll
        for (int r = 0; r < 16; r++)
            acc[r] += xs[half_ * 16 + r][k] * wv;
    }
    #pragma unroll
    for (int r = 0; r < 16; r++) {
        int row = row0 + half_ * 16 + r;
        g_h[(size_t)row * D + d] = __float2half(acc[r] * g_dinv[row]);
    }
}

// ---------------------------------------------------------------------------
// Kernel 2: out = dinv ⊙ (A @ g) + bias via mma.sync fp16 (fp32 accumulate).
// grid 256 CTAs (M=32 each), 256 threads (8 warps: 2 row x 4 col).
// 2 CTAs/SM (80KB smem each) so stalls in one pipeline are covered by the
// other. KC=128 stages (two 64-k sub-tiles), double-buffered.
// ---------------------------------------------------------------------------
__global__ void __launch_bounds__(256, 2) gemm_kernel(const float* __restrict__ adj,
                                                      const float* __restrict__ bias,
                                                      float* __restrict__ out) {
    extern __shared__ __align__(16) unsigned char smbuf[];
    const uint32_t sm = smem_u32(smbuf);

    const int tid = threadIdx.x;
    const int lane = tid & 31;
    const int wid = tid >> 5;
    const int wr = wid & 1;          // warp row  (16 rows)
    const int wc = wid >> 1;         // warp col  (32 cols)
    const int row0 = blockIdx.x * MT;

    // ---- A loader mapping (per 64-k sub-tile): 8 floats per thread ----
    const int am = tid >> 3;                 // 0..31  A row within tile
    const int aks = (tid & 7) * 8;           // A k-offset (8 floats)
    const uint32_t axor_st = (uint32_t)(am & 7) << 4;
    const uint32_t a_st_off = (((uint32_t)am * 64 + aks) * 2) ^ axor_st;

    // ---- B loader mapping (per 64-k sub-tile): 4 x cp.async16 ----
    const int bk = tid >> 2;                 // 0..63  B k-row within sub-tile
    const int bnc0 = (tid & 3) * 4;          // 4 chunks of 8 halves
    const uint32_t bxor_st = (uint32_t)(bk & 7) << 4;
    uint32_t b_st_off[4];
    #pragma unroll
    for (int j = 0; j < 4; j++)
        b_st_off[j] = (((uint32_t)bk * D + (bnc0 + j) * 8) * 2) ^ bxor_st;
    const __half* bptr = g_h + (size_t)bk * D + bnc0 * 8;

    // ---- mma fragment address components (fixed per lane) ----
    const int arow_f = wr * 16 + (lane & 15);
    const uint32_t axor_f = (uint32_t)(arow_f & 7) << 4;
    const int akl8 = (lane >> 4) * 8;
    const int brow_l = (lane & 7) + ((lane >> 3) & 1) * 8;
    const uint32_t bxor_f = (uint32_t)(lane & 7) << 4;
    const int bnl8 = (lane >> 4) * 8;
    const int n0w = wc * 32;

    float c[4][4];
    #pragma unroll
    for (int j = 0; j < 4; j++)
        #pragma unroll
        for (int q = 0; q < 4; q++) c[j][q] = 0.f;

    const float* arow_ptr = adj + (size_t)(row0 + am) * N_NODES;

    // ---- prologue: prefetch stage 0 (A->regs, B->cp.async) ----
    float4 apre[2][2];
    #pragma unroll
    for (int h = 0; h < 2; h++) {
        const float4* ap = reinterpret_cast<const float4*>(arow_ptr + h * 64 + aks);
        apre[h][0] = ap[0];
        apre[h][1] = ap[1];
    }
    {
        #pragma unroll
        for (int h = 0; h < 2; h++) {
            uint32_t bbase = sm + 2 * A_SUB_BYTES + (uint32_t)h * B_SUB_BYTES;
            const __half* bp = bptr + (size_t)h * 64 * D;
            #pragma unroll
            for (int j = 0; j < 4; j++)
                cp_async16(bbase + b_st_off[j], bp + j * 8);
        }
        cp_commit();
    }

    for (int i = 0; i < NITER; i++) {
        const int s = i & 1;
        const uint32_t sA = sm + (uint32_t)s * STAGE_BYTES;
        const uint32_t sB = sA + 2 * A_SUB_BYTES;

        // STS A_i (convert fp32 regs -> fp16, both sub-tiles)
        #pragma unroll
        for (int h = 0; h < 2; h++) {
            uint4 v;
            v.x = h2u(__floats2half2_rn(apre[h][0].x, apre[h][0].y));
            v.y = h2u(__floats2half2_rn(apre[h][0].z, apre[h][0].w));
            v.z = h2u(__floats2half2_rn(apre[h][1].x, apre[h][1].y));
            v.w = h2u(__floats2half2_rn(apre[h][1].z, apre[h][1].w));
            sts128(sA + (uint32_t)h * A_SUB_BYTES + a_st_off, v);
        }

        cp_wait0();          // B_i resident
        __syncthreads();     // A_i visible; prior compute done

        // prefetch stage i+1 (overlaps compute below)
        if (i + 1 < NITER) {
            const float* arp = arow_ptr + (size_t)(i + 1) * KC;
            #pragma unroll
            for (int h = 0; h < 2; h++) {
                const float4* ap = reinterpret_cast<const float4*>(arp + h * 64 + aks);
                apre[h][0] = ap[0];
                apre[h][1] = ap[1];
            }
            uint32_t bstage = sm + (uint32_t)(s ^ 1) * STAGE_BYTES + 2 * A_SUB_BYTES;
            const __half* bp0 = bptr + (size_t)(i + 1) * KC * D;
            #pragma unroll
            for (int h = 0; h < 2; h++) {
                uint32_t bbase = bstage + (uint32_t)h * B_SUB_BYTES;
                const __half* bp = bp0 + (size_t)h * 64 * D;
                #pragma unroll
                for (int j = 0; j < 4; j++)
                    cp_async16(bbase + b_st_off[j], bp + j * 8);
            }
            cp_commit();
        }

        // compute stage i: 2 sub-tiles x 4 k16 steps
        #pragma unroll
        for (int h = 0; h < 2; h++) {
            const uint32_t sAh = sA + (uint32_t)h * A_SUB_BYTES;
            const uint32_t sBh = sB + (uint32_t)h * B_SUB_BYTES;
            #pragma unroll
            for (int s16 = 0; s16 < 4; s16++) {
                const int k0 = s16 * 16;
                uint32_t ra[4];
                uint32_t aaddr = sAh + ((((uint32_t)arow_f * 64 + k0 + akl8) * 2) ^ axor_f);
                ldsm_x4(ra, aaddr);
                #pragma unroll
                for (int nb = 0; nb < 2; nb++) {
                    uint32_t rb[4];
                    uint32_t baddr = sBh +
                        ((((uint32_t)(k0 + brow_l) * D + n0w + nb * 16 + bnl8) * 2) ^ bxor_f);
                    ldsm_x4_t(rb, baddr);
                    mma16816(c[nb * 2 + 0], ra, rb[0], rb[1]);
                    mma16816(c[nb * 2 + 1], ra, rb[2], rb[3]);
                }
            }
        }
    }

    // ---- epilogue: out = c * dinv[row] + bias[col] ----
    const int grp = lane >> 2, tid4 = lane & 3;
    const int r1 = row0 + wr * 16 + grp;
    const int r2 = r1 + 8;
    const float d1 = g_dinv[r1], d2 = g_dinv[r2];
    #pragma unroll
    for (int j = 0; j < 4; j++) {
        int col = n0w + j * 8 + tid4 * 2;
        float b0 = bias[col], b1 = bias[col + 1];
        float2 o1, o2;
        o1.x = fmaf(c[j][0], d1, b0);
        o1.y = fmaf(c[j][1], d1, b1);
        o2.x = fmaf(c[j][2], d2, b0);
        o2.y = fmaf(c[j][3], d2, b1);
        *reinterpret_cast<float2*>(out + (size_t)r1 * D + col) = o1;
        *reinterpret_cast<float2*>(out + (size_t)r2 * D + col) = o2;
    }
}

// ---------------------------------------------------------------------------
extern "C" void kernel_launch(void* const* d_in, const int* in_sizes, int n_in,
                              void* d_out, int out_size) {
    const float* x = nullptr;
    const float* adj = nullptr;
    const float* weight = nullptr;
    const float* bias = nullptr;
    for (int i = 0; i < n_in; i++) {
        long long sz = in_sizes[i];
        if (sz == (long long)N_NODES * N_NODES) adj = (const float*)d_in[i];
        else if (sz == (long long)N_NODES * D)  x = (const float*)d_in[i];
        else if (sz == (long long)D * D)        weight = (const float*)d_in[i];
        else if (sz == D)                       bias = (const float*)d_in[i];
    }
    float* out = (float*)d_out;

    cudaFuncSetAttribute(gemm_kernel,
                         cudaFuncAttributeMaxDynamicSharedMemorySize, SMEM_BYTES);

    rowsum_kernel<<<N_NODES, 256>>>(adj);
    proj_kernel<<<N_NODES / 32, 256>>>(x, weight);
    gemm_kernel<<<N_NODES / MT, 256, SMEM_BYTES>>>(adj, bias, out);
}

// round 7
// speedup vs baseline: 1.0531x; 1.0531x over previous
#include <cuda_runtime.h>
#include <cuda_fp16.h>
#include <cstdint>
#include <cstddef>
#include <cstring>

#define N_NODES 8192
#define D 128
#define MT 32                        // M rows per CTA
#define KCG 64                       // K per pipeline stage
#define NSTAGE 4
#define NITER (N_NODES / KCG)        // 128
#define A_TILE_B (MT * KCG * 2)          // 4096
#define B_TILE_B (KCG * D * 2)           // 16384
#define STAGE_B (A_TILE_B + B_TILE_B)    // 20480
#define SMEM_BYTES (NSTAGE * STAGE_B)    // 81920

// ---------------- device scratch ----------------
__device__ float g_dinv[N_NODES];
__device__ __half g_ah[(size_t)N_NODES * N_NODES];  // fp16 copy of adj (128MB)
__device__ __half g_h[(size_t)N_NODES * D];         // dinv-scaled proj, fp16 [k][n]

// ---------------- helpers ----------------
__device__ __forceinline__ uint32_t smem_u32(const void* p) {
    uint32_t a;
    asm("{ .reg .u64 t; cvta.to.shared.u64 t, %1; cvt.u32.u64 %0, t; }" : "=r"(a) : "l"(p));
    return a;
}
__device__ __forceinline__ void cp_async16(uint32_t dst, const void* src) {
    asm volatile("cp.async.cg.shared.global [%0], [%1], 16;" :: "r"(dst), "l"(src));
}
__device__ __forceinline__ void cp_commit() {
    asm volatile("cp.async.commit_group;" ::: "memory");
}
__device__ __forceinline__ void cp_wait2() {
    asm volatile("cp.async.wait_group 2;" ::: "memory");
}
__device__ __forceinline__ void ldsm_x4(uint32_t* r, uint32_t a) {
    asm volatile("ldmatrix.sync.aligned.m8n8.x4.shared.b16 {%0,%1,%2,%3}, [%4];"
                 : "=r"(r[0]), "=r"(r[1]), "=r"(r[2]), "=r"(r[3]) : "r"(a));
}
__device__ __forceinline__ void ldsm_x4_t(uint32_t* r, uint32_t a) {
    asm volatile("ldmatrix.sync.aligned.m8n8.x4.trans.shared.b16 {%0,%1,%2,%3}, [%4];"
                 : "=r"(r[0]), "=r"(r[1]), "=r"(r[2]), "=r"(r[3]) : "r"(a));
}
__device__ __forceinline__ void mma16816(float* c, const uint32_t* a, uint32_t b0, uint32_t b1) {
    asm volatile(
        "mma.sync.aligned.m16n8k16.row.col.f32.f16.f16.f32 "
        "{%0,%1,%2,%3},{%4,%5,%6,%7},{%8,%9},{%0,%1,%2,%3};"
        : "+f"(c[0]), "+f"(c[1]), "+f"(c[2]), "+f"(c[3])
        : "r"(a[0]), "r"(a[1]), "r"(a[2]), "r"(a[3]), "r"(b0), "r"(b1));
}
__device__ __forceinline__ uint32_t h2u(__half2 h) {
    uint32_t u; __builtin_memcpy(&u, &h, 4); return u;
}

// ---------------------------------------------------------------------------
// Kernel 0: fused rowsum + fp16 convert of adj.
// One block per row: sum the row AND write the fp16 copy (coalesced 8B stores).
// ---------------------------------------------------------------------------
__global__ void __launch_bounds__(256) rowsum_cvt_kernel(const float* __restrict__ adj) {
    int row = blockIdx.x;
    const float4* p = reinterpret_cast<const float4*>(adj + (size_t)row * N_NODES);
    uint2* q = reinterpret_cast<uint2*>(g_ah + (size_t)row * N_NODES);
    float s = 0.f;
    #pragma unroll 8
    for (int i = threadIdx.x; i < N_NODES / 4; i += 256) {
        float4 v = p[i];
        s += (v.x + v.y) + (v.z + v.w);
        uint2 h;
        h.x = h2u(__floats2half2_rn(v.x, v.y));
        h.y = h2u(__floats2half2_rn(v.z, v.w));
        q[i] = h;
    }
    #pragma unroll
    for (int o = 16; o > 0; o >>= 1) s += __shfl_down_sync(0xffffffffu, s, o);
    __shared__ float red[8];
    int lane = threadIdx.x & 31, wid = threadIdx.x >> 5;
    if (lane == 0) red[wid] = s;
    __syncthreads();
    if (wid == 0) {
        s = (lane < 8) ? red[lane] : 0.f;
        #pragma unroll
        for (int o = 4; o > 0; o >>= 1) s += __shfl_down_sync(0xffffffffu, s, o);
        if (lane == 0) g_dinv[row] = (s > 0.f) ? rsqrtf(s) : 0.f;
    }
}

// ---------------------------------------------------------------------------
// Kernel 1: g_h[k][n] = fp16( dinv[k] * (x[k,:] @ W)[n] )
// ---------------------------------------------------------------------------
__global__ void __launch_bounds__(256) proj_kernel(const float* __restrict__ x,
                                                   const float* __restrict__ w) {
    __shared__ float xs[32][D];
    int row0 = blockIdx.x * 32;
    int tid = threadIdx.x;
    for (int i = tid; i < 32 * D; i += 256)
        xs[i / D][i % D] = x[(size_t)(row0 + i / D) * D + (i % D)];
    __syncthreads();

    int d = tid & 127;
    int half_ = tid >> 7;
    float acc[16];
    #pragma unroll
    for (int r = 0; r < 16; r++) acc[r] = 0.f;

    for (int k = 0; k < D; k++) {
        float wv = w[k * D + d];
        #pragma unroll
        for (int r = 0; r < 16; r++)
            acc[r] += xs[half_ * 16 + r][k] * wv;
    }
    #pragma unroll
    for (int r = 0; r < 16; r++) {
        int row = row0 + half_ * 16 + r;
        g_h[(size_t)row * D + d] = __float2half(acc[r] * g_dinv[row]);
    }
}

// ---------------------------------------------------------------------------
// Kernel 2: pure fp16 GEMM via mma.sync (fp32 accum), all loads cp.async.
// grid 256 CTAs (M=32), 256 threads (8 warps 2x4, warp tile 16x32), occ 2.
// 4-deep stage ring (KC=64, 20KB/stage), cp.async.wait_group 2.
// Epilogue fuses dinv row-scale + bias.
// ---------------------------------------------------------------------------
__global__ void __launch_bounds__(256, 2) gemm_kernel(const float* __restrict__ bias,
                                                      float* __restrict__ out) {
    extern __shared__ __align__(16) unsigned char smbuf[];
    const uint32_t sm = smem_u32(smbuf);

    const int tid = threadIdx.x;
    const int lane = tid & 31;
    const int wid = tid >> 5;
    const int wr = wid & 1;          // warp row  (16 rows)
    const int wc = wid >> 1;         // warp col  (32 cols)
    const int row0 = blockIdx.x * MT;

    // ---- A loader: 1 cp.async16 per thread per stage ----
    const int am = tid >> 3;                 // 0..31 row
    const int ak = (tid & 7) * 8;            // k offset (8 halves = 16B)
    const uint32_t a_off = (((uint32_t)am * KCG + ak) * 2) ^ ((uint32_t)(am & 7) << 4);
    const __half* asrc = g_ah + (size_t)(row0 + am) * N_NODES + ak;

    // ---- B loader: 4 cp.async16 per thread per stage ----
    const int bk = tid >> 2;                 // 0..63 k row
    const int bnc0 = (tid & 3) * 4;          // 4 chunks of 8 halves
    uint32_t b_off[4];
    #pragma unroll
    for (int j = 0; j < 4; j++)
        b_off[j] = (((uint32_t)bk * D + (bnc0 + j) * 8) * 2) ^ ((uint32_t)(bk & 7) << 4);
    const __half* bsrc = g_h + (size_t)bk * D + bnc0 * 8;

    // ---- mma fragment addressing (fixed per lane) ----
    const int arow_f = wr * 16 + (lane & 15);
    const uint32_t axor_f = (uint32_t)(arow_f & 7) << 4;
    const int akl8 = (lane >> 4) * 8;
    const int brow_l = (lane & 7) + ((lane >> 3) & 1) * 8;
    const uint32_t bxor_f = (uint32_t)(lane & 7) << 4;
    const int bnl8 = (lane >> 4) * 8;
    const int n0w = wc * 32;

    float c[4][4];
    #pragma unroll
    for (int j = 0; j < 4; j++)
        #pragma unroll
        for (int q = 0; q < 4; q++) c[j][q] = 0.f;

    // ---- prologue: issue stages 0..2 ----
    #pragma unroll
    for (int p = 0; p < NSTAGE - 1; p++) {
        uint32_t base = sm + (uint32_t)p * STAGE_B;
        cp_async16(base + a_off, asrc + (size_t)p * KCG);
        #pragma unroll
        for (int j = 0; j < 4; j++)
            cp_async16(base + A_TILE_B + b_off[j], bsrc + (size_t)p * KCG * D + j * 8);
        cp_commit();
    }

    for (int i = 0; i < NITER; i++) {
        cp_wait2();          // stage i resident (i+1, i+2 may be pending)
        __syncthreads();

        // issue stage i+3 into ring slot (i+3)&3 (== slot of finished stage i-1)
        if (i + NSTAGE - 1 < NITER) {
            int p = i + NSTAGE - 1;
            uint32_t base = sm + (uint32_t)(p & (NSTAGE - 1)) * STAGE_B;
            cp_async16(base + a_off, asrc + (size_t)p * KCG);
            #pragma unroll
            for (int j = 0; j < 4; j++)
                cp_async16(base + A_TILE_B + b_off[j], bsrc + (size_t)p * KCG * D + j * 8);
        }
        cp_commit();

        // compute stage i: 4 k16 steps
        const uint32_t sA = sm + (uint32_t)(i & (NSTAGE - 1)) * STAGE_B;
        const uint32_t sB = sA + A_TILE_B;
        #pragma unroll
        for (int s16 = 0; s16 < 4; s16++) {
            const int k0 = s16 * 16;
            uint32_t ra[4];
            ldsm_x4(ra, sA + ((((uint32_t)arow_f * KCG + k0 + akl8) * 2) ^ axor_f));
            #pragma unroll
            for (int nb = 0; nb < 2; nb++) {
                uint32_t rb[4];
                ldsm_x4_t(rb, sB + ((((uint32_t)(k0 + brow_l) * D + n0w + nb * 16 + bnl8) * 2) ^ bxor_f));
                mma16816(c[nb * 2 + 0], ra, rb[0], rb[1]);
                mma16816(c[nb * 2 + 1], ra, rb[2], rb[3]);
            }
        }
    }

    // ---- epilogue: out = c * dinv[row] + bias[col] ----
    const int grp = lane >> 2, tid4 = lane & 3;
    const int r1 = row0 + wr * 16 + grp;
    const int r2 = r1 + 8;
    const float d1 = g_dinv[r1], d2 = g_dinv[r2];
    #pragma unroll
    for (int j = 0; j < 4; j++) {
        int col = n0w + j * 8 + tid4 * 2;
        float b0 = bias[col], b1 = bias[col + 1];
        float2 o1, o2;
        o1.x = fmaf(c[j][0], d1, b0);
        o1.y = fmaf(c[j][1], d1, b1);
        o2.x = fmaf(c[j][2], d2, b0);
        o2.y = fmaf(c[j][3], d2, b1);
        *reinterpret_cast<float2*>(out + (size_t)r1 * D + col) = o1;
        *reinterpret_cast<float2*>(out + (size_t)r2 * D + col) = o2;
    }
}

// ---------------------------------------------------------------------------
extern "C" void kernel_launch(void* const* d_in, const int* in_sizes, int n_in,
                              void* d_out, int out_size) {
    const float* x = nullptr;
    const float* adj = nullptr;
    const float* weight = nullptr;
    const float* bias = nullptr;
    for (int i = 0; i < n_in; i++) {
        long long sz = in_sizes[i];
        if (sz == (long long)N_NODES * N_NODES) adj = (const float*)d_in[i];
        else if (sz == (long long)N_NODES * D)  x = (const float*)d_in[i];
        else if (sz == (long long)D * D)        weight = (const float*)d_in[i];
        else if (sz == D)                       bias = (const float*)d_in[i];
    }
    float* out = (float*)d_out;

    cudaFuncSetAttribute(gemm_kernel,
                         cudaFuncAttributeMaxDynamicSharedMemorySize, SMEM_BYTES);

    rowsum_cvt_kernel<<<N_NODES, 256>>>(adj);
    proj_kernel<<<N_NODES / 32, 256>>>(x, weight);
    gemm_kernel<<<N_NODES / MT, 256, SMEM_BYTES>>>(bias, out);
}

// round 9
// speedup vs baseline: 1.0849x; 1.0302x over previous
#include <cuda_runtime.h>
#include <cuda_fp16.h>
#include <cstdint>
#include <cstddef>
#include <cstring>

#define N_NODES 8192
#define D 128
#define MT 32                        // M rows per CTA
#define KCG 64                       // K per pipeline stage
#define NITER 128                    // N_NODES / KCG
#define A_TILE_B (MT * KCG * 2)          // 4096
#define B_TILE_B (KCG * D * 2)           // 16384
#define STAGE_B (A_TILE_B + B_TILE_B)    // 20480
#define SMEM_BYTES (4 * STAGE_B)         // 81920

// ---------------- device scratch ----------------
__device__ float g_dinv[N_NODES];
__device__ __half g_ah[(size_t)N_NODES * N_NODES];  // fp16 copy of adj (128MB)
__device__ __half g_h[(size_t)N_NODES * D];         // dinv-scaled proj, fp16 [k][n]

// ---------------- helpers ----------------
__device__ __forceinline__ uint32_t smem_u32(const void* p) {
    uint32_t a;
    asm("{ .reg .u64 t; cvta.to.shared.u64 t, %1; cvt.u32.u64 %0, t; }" : "=r"(a) : "l"(p));
    return a;
}
__device__ __forceinline__ void cp_async16(uint32_t dst, const void* src) {
    asm volatile("cp.async.cg.shared.global [%0], [%1], 16;" :: "r"(dst), "l"(src));
}
__device__ __forceinline__ void cp_commit() {
    asm volatile("cp.async.commit_group;" ::: "memory");
}
__device__ __forceinline__ void cp_wait2() {
    asm volatile("cp.async.wait_group 2;" ::: "memory");
}
__device__ __forceinline__ void ldsm_x4(uint32_t* r, uint32_t a) {
    asm volatile("ldmatrix.sync.aligned.m8n8.x4.shared.b16 {%0,%1,%2,%3}, [%4];"
                 : "=r"(r[0]), "=r"(r[1]), "=r"(r[2]), "=r"(r[3]) : "r"(a));
}
__device__ __forceinline__ void ldsm_x4_t(uint32_t* r, uint32_t a) {
    asm volatile("ldmatrix.sync.aligned.m8n8.x4.trans.shared.b16 {%0,%1,%2,%3}, [%4];"
                 : "=r"(r[0]), "=r"(r[1]), "=r"(r[2]), "=r"(r[3]) : "r"(a));
}
__device__ __forceinline__ void mma16816(float* c, const uint32_t* a, uint32_t b0, uint32_t b1) {
    asm volatile(
        "mma.sync.aligned.m16n8k16.row.col.f32.f16.f16.f32 "
        "{%0,%1,%2,%3},{%4,%5,%6,%7},{%8,%9},{%0,%1,%2,%3};"
        : "+f"(c[0]), "+f"(c[1]), "+f"(c[2]), "+f"(c[3])
        : "r"(a[0]), "r"(a[1]), "r"(a[2]), "r"(a[3]), "r"(b0), "r"(b1));
}
__device__ __forceinline__ uint32_t h2u(__half2 h) {
    uint32_t u; __builtin_memcpy(&u, &h, 4); return u;
}

// ---------------------------------------------------------------------------
// Kernel 0: fused rowsum + fp16 convert of adj (82.9% DRAM — near roofline)
// ---------------------------------------------------------------------------
__global__ void __launch_bounds__(256) rowsum_cvt_kernel(const float* __restrict__ adj) {
    int row = blockIdx.x;
    const float4* p = reinterpret_cast<const float4*>(adj + (size_t)row * N_NODES);
    uint2* q = reinterpret_cast<uint2*>(g_ah + (size_t)row * N_NODES);
    float s = 0.f;
    #pragma unroll 8
    for (int i = threadIdx.x; i < N_NODES / 4; i += 256) {
        float4 v = p[i];
        s += (v.x + v.y) + (v.z + v.w);
        uint2 h;
        h.x = h2u(__floats2half2_rn(v.x, v.y));
        h.y = h2u(__floats2half2_rn(v.z, v.w));
        q[i] = h;
    }
    #pragma unroll
    for (int o = 16; o > 0; o >>= 1) s += __shfl_down_sync(0xffffffffu, s, o);
    __shared__ float red[8];
    int lane = threadIdx.x & 31, wid = threadIdx.x >> 5;
    if (lane == 0) red[wid] = s;
    __syncthreads();
    if (wid == 0) {
        s = (lane < 8) ? red[lane] : 0.f;
        #pragma unroll
        for (int o = 4; o > 0; o >>= 1) s += __shfl_down_sync(0xffffffffu, s, o);
        if (lane == 0) g_dinv[row] = (s > 0.f) ? rsqrtf(s) : 0.f;
    }
}

// ---------------------------------------------------------------------------
// Kernel 1: g_h[k][n] = fp16( dinv[k] * (x[k,:] @ W)[n] )
// ---------------------------------------------------------------------------
__global__ void __launch_bounds__(256) proj_kernel(const float* __restrict__ x,
                                                   const float* __restrict__ w) {
    __shared__ float xs[32][D];
    int row0 = blockIdx.x * 32;
    int tid = threadIdx.x;
    for (int i = tid; i < 32 * D; i += 256)
        xs[i / D][i % D] = x[(size_t)(row0 + i / D) * D + (i % D)];
    __syncthreads();

    int d = tid & 127;
    int half_ = tid >> 7;
    float acc[16];
    #pragma unroll
    for (int r = 0; r < 16; r++) acc[r] = 0.f;

    for (int k = 0; k < D; k++) {
        float wv = w[k * D + d];
        #pragma unroll
        for (int r = 0; r < 16; r++)
            acc[r] += xs[half_ * 16 + r][k] * wv;
    }
    #pragma unroll
    for (int r = 0; r < 16; r++) {
        int row = row0 + half_ * 16 + r;
        g_h[(size_t)row * D + d] = __float2half(acc[r] * g_dinv[row]);
    }
}

// ---------------------------------------------------------------------------
// Kernel 2: pure fp16 GEMM via mma.sync (fp32 accum).
// grid 256 CTAs (M=32), 256 threads (8 warps 2x4), occ 2.
// Round-7 pipeline semantics (proven correct): per stage i —
//   wait_group 2 ; __syncthreads ; issue stage i+3 into slot (i+3)&3
//   (that slot held stage i-1, whose compute finished before this sync) ;
//   unconditional commit ; compute stage i.
// Unrolled x4 so all slot addresses are compile-time static.
// ---------------------------------------------------------------------------
__global__ void __launch_bounds__(256, 2) gemm_kernel(const float* __restrict__ bias,
                                                      float* __restrict__ out) {
    extern __shared__ __align__(16) unsigned char smbuf[];
    const uint32_t sm = smem_u32(smbuf);

    const int tid = threadIdx.x;
    const int lane = tid & 31;
    const int wid = tid >> 5;
    const int wr = wid & 1;          // warp row  (16 rows)
    const int wc = wid >> 1;         // warp col  (32 cols)
    const int row0 = blockIdx.x * MT;

    // ---- A loader: 1 cp.async16 per thread per stage ----
    const int am = tid >> 3;
    const int ak = (tid & 7) * 8;
    const uint32_t a_off = (((uint32_t)am * KCG + ak) * 2) ^ ((uint32_t)(am & 7) << 4);
    const __half* asrc = g_ah + (size_t)(row0 + am) * N_NODES + ak;

    // ---- B loader: 4 cp.async16 per thread per stage ----
    const int bk = tid >> 2;
    const int bnc0 = (tid & 3) * 4;
    uint32_t b_off[4];
    #pragma unroll
    for (int j = 0; j < 4; j++)
        b_off[j] = (((uint32_t)bk * D + (bnc0 + j) * 8) * 2) ^ ((uint32_t)(bk & 7) << 4);
    const __half* bsrc = g_h + (size_t)bk * D + bnc0 * 8;

    // ---- mma fragment addressing (fixed per lane) ----
    const int arow_f = wr * 16 + (lane & 15);
    const uint32_t axor_f = (uint32_t)(arow_f & 7) << 4;
    const uint32_t aoff_l = ((uint32_t)arow_f * KCG + (lane >> 4) * 8) * 2;
    const int brow_l = (lane & 7) + ((lane >> 3) & 1) * 8;
    const uint32_t bxor_f = (uint32_t)(lane & 7) << 4;
    const uint32_t boff_l = ((uint32_t)brow_l * D + wc * 32 + (lane >> 4) * 8) * 2;
    const int n0w = wc * 32;

    float c[4][4];
    #pragma unroll
    for (int j = 0; j < 4; j++)
        #pragma unroll
        for (int q = 0; q < 4; q++) c[j][q] = 0.f;

    // issue one stage's loads into ring slot base (no commit inside)
    #define ISSUE_STAGE(base, p)                                                   \
        do {                                                                       \
            cp_async16((base) + a_off, asrc + (size_t)(p) * KCG);                  \
            const __half* _bp = bsrc + (size_t)(p) * KCG * D;                      \
            cp_async16((base) + A_TILE_B + b_off[0], _bp);                         \
            cp_async16((base) + A_TILE_B + b_off[1], _bp + 8);                     \
            cp_async16((base) + A_TILE_B + b_off[2], _bp + 16);                    \
            cp_async16((base) + A_TILE_B + b_off[3], _bp + 24);                    \
        } while (0)

    #define COMPUTE_STAGE(sA, sB)                                                  \
        do {                                                                       \
            _Pragma("unroll")                                                      \
            for (int s16 = 0; s16 < 4; s16++) {                                    \
                uint32_t ra[4];                                                    \
                ldsm_x4(ra, (sA) + ((aoff_l + 32u * s16) ^ axor_f));               \
                uint32_t rb0[4], rb1[4];                                           \
                ldsm_x4_t(rb0, (sB) + ((boff_l + 4096u * s16) ^ bxor_f));          \
                ldsm_x4_t(rb1, (sB) + ((boff_l + 4096u * s16 + 32u) ^ bxor_f));    \
                mma16816(c[0], ra, rb0[0], rb0[1]);                                \
                mma16816(c[1], ra, rb0[2], rb0[3]);                                \
                mma16816(c[2], ra, rb1[0], rb1[1]);                                \
                mma16816(c[3], ra, rb1[2], rb1[3]);                                \
            }                                                                      \
        } while (0)

    // one pipeline step, round-7 order, static slot addresses
    #define STEP(slot_issue, slot_comp, p_issue)                                   \
        do {                                                                       \
            cp_wait2();                                                            \
            __syncthreads();                                                       \
            if ((p_issue) < NITER) ISSUE_STAGE(slot_issue, p_issue);               \
            cp_commit();                                                           \
            COMPUTE_STAGE(slot_comp, (slot_comp) + A_TILE_B);                      \
        } while (0)

    const uint32_t s0 = sm;
    const uint32_t s1 = sm + STAGE_B;
    const uint32_t s2 = sm + 2 * STAGE_B;
    const uint32_t s3 = sm + 3 * STAGE_B;

    // ---- prologue: fill 3 stages ----
    ISSUE_STAGE(s0, 0); cp_commit();
    ISSUE_STAGE(s1, 1); cp_commit();
    ISSUE_STAGE(s2, 2); cp_commit();

    // ---- main loop: 32 x 4 stages ----
    for (int j = 0; j < 32; j++) {
        const int p = 4 * j;
        STEP(s3, s0, p + 3);     // compute stage p   (slot0), issue p+3 -> slot3
        STEP(s0, s1, p + 4);     // compute stage p+1 (slot1), issue p+4 -> slot0
        STEP(s1, s2, p + 5);     // compute stage p+2 (slot2), issue p+5 -> slot1
        STEP(s2, s3, p + 6);     // compute stage p+3 (slot3), issue p+6 -> slot2
    }

    // ---- epilogue: out = c * dinv[row] + bias[col] ----
    const int grp = lane >> 2, tid4 = lane & 3;
    const int r1 = row0 + wr * 16 + grp;
    const int r2 = r1 + 8;
    const float d1 = g_dinv[r1], d2 = g_dinv[r2];
    #pragma unroll
    for (int j = 0; j < 4; j++) {
        int col = n0w + j * 8 + tid4 * 2;
        float b0 = bias[col], b1 = bias[col + 1];
        float2 o1, o2;
        o1.x = fmaf(c[j][0], d1, b0);
        o1.y = fmaf(c[j][1], d1, b1);
        o2.x = fmaf(c[j][2], d2, b0);
        o2.y = fmaf(c[j][3], d2, b1);
        *reinterpret_cast<float2*>(out + (size_t)r1 * D + col) = o1;
        *reinterpret_cast<float2*>(out + (size_t)r2 * D + col) = o2;
    }
    #undef ISSUE_STAGE
    #undef COMPUTE_STAGE
    #undef STEP
}

// ---------------------------------------------------------------------------
extern "C" void kernel_launch(void* const* d_in, const int* in_sizes, int n_in,
                              void* d_out, int out_size) {
    const float* x = nullptr;
    const float* adj = nullptr;
    const float* weight = nullptr;
    const float* bias = nullptr;
    for (int i = 0; i < n_in; i++) {
        long long sz = in_sizes[i];
        if (sz == (long long)N_NODES * N_NODES) adj = (const float*)d_in[i];
        else if (sz == (long long)N_NODES * D)  x = (const float*)d_in[i];
        else if (sz == (long long)D * D)        weight = (const float*)d_in[i];
        else if (sz == D)                       bias = (const float*)d_in[i];
    }
    float* out = (float*)d_out;

    cudaFuncSetAttribute(gemm_kernel,
                         cudaFuncAttributeMaxDynamicSharedMemorySize, SMEM_BYTES);

    rowsum_cvt_kernel<<<N_NODES, 256>>>(adj);
    proj_kernel<<<N_NODES / 32, 256>>>(x, weight);
    gemm_kernel<<<N_NODES / MT, 256, SMEM_BYTES>>>(bias, out);
}

// round 10
// speedup vs baseline: 1.3067x; 1.2045x over previous
#include <cuda_runtime.h>
#include <cuda_fp16.h>
#include <cstdint>
#include <cstddef>
#include <cstring>

#define N_NODES 8192
#define D 128
#define MT 64                        // M rows per CTA
#define NSPLIT 2
#define KSPLIT (N_NODES / NSPLIT)    // 4096
#define KCG 64                       // K per pipeline stage
#define NITER_S (KSPLIT / KCG)       // 64
#define A_TILE_B (MT * KCG * 2)          // 8192
#define B_TILE_B (KCG * D * 2)           // 16384
#define STAGE_B (A_TILE_B + B_TILE_B)    // 24576
#define SMEM_BYTES (4 * STAGE_B)         // 98304

// ---------------- device scratch ----------------
__device__ float g_dinv[N_NODES];
__device__ __half g_ah[(size_t)N_NODES * N_NODES];   // fp16 copy of adj (128MB)
__device__ __half g_h[(size_t)N_NODES * D];          // dinv-scaled proj, fp16 [k][n]
__device__ float g_part[(size_t)NSPLIT * N_NODES * D];  // split-K partials (8MB)

// ---------------- helpers ----------------
__device__ __forceinline__ uint32_t smem_u32(const void* p) {
    uint32_t a;
    asm("{ .reg .u64 t; cvta.to.shared.u64 t, %1; cvt.u32.u64 %0, t; }" : "=r"(a) : "l"(p));
    return a;
}
__device__ __forceinline__ void cp_async16(uint32_t dst, const void* src) {
    asm volatile("cp.async.cg.shared.global [%0], [%1], 16;" :: "r"(dst), "l"(src));
}
__device__ __forceinline__ void cp_commit() {
    asm volatile("cp.async.commit_group;" ::: "memory");
}
__device__ __forceinline__ void cp_wait2() {
    asm volatile("cp.async.wait_group 2;" ::: "memory");
}
__device__ __forceinline__ void ldsm_x4(uint32_t* r, uint32_t a) {
    asm volatile("ldmatrix.sync.aligned.m8n8.x4.shared.b16 {%0,%1,%2,%3}, [%4];"
                 : "=r"(r[0]), "=r"(r[1]), "=r"(r[2]), "=r"(r[3]) : "r"(a));
}
__device__ __forceinline__ void ldsm_x4_t(uint32_t* r, uint32_t a) {
    asm volatile("ldmatrix.sync.aligned.m8n8.x4.trans.shared.b16 {%0,%1,%2,%3}, [%4];"
                 : "=r"(r[0]), "=r"(r[1]), "=r"(r[2]), "=r"(r[3]) : "r"(a));
}
__device__ __forceinline__ void mma16816(float* c, const uint32_t* a, uint32_t b0, uint32_t b1) {
    asm volatile(
        "mma.sync.aligned.m16n8k16.row.col.f32.f16.f16.f32 "
        "{%0,%1,%2,%3},{%4,%5,%6,%7},{%8,%9},{%0,%1,%2,%3};"
        : "+f"(c[0]), "+f"(c[1]), "+f"(c[2]), "+f"(c[3])
        : "r"(a[0]), "r"(a[1]), "r"(a[2]), "r"(a[3]), "r"(b0), "r"(b1));
}
__device__ __forceinline__ uint32_t h2u(__half2 h) {
    uint32_t u; __builtin_memcpy(&u, &h, 4); return u;
}

// ---------------------------------------------------------------------------
// Kernel 0: fused rowsum + fp16 convert of adj (82-84% DRAM — near roofline)
// ---------------------------------------------------------------------------
__global__ void __launch_bounds__(256) rowsum_cvt_kernel(const float* __restrict__ adj) {
    int row = blockIdx.x;
    const float4* p = reinterpret_cast<const float4*>(adj + (size_t)row * N_NODES);
    uint2* q = reinterpret_cast<uint2*>(g_ah + (size_t)row * N_NODES);
    float s = 0.f;
    #pragma unroll 8
    for (int i = threadIdx.x; i < N_NODES / 4; i += 256) {
        float4 v = p[i];
        s += (v.x + v.y) + (v.z + v.w);
        uint2 h;
        h.x = h2u(__floats2half2_rn(v.x, v.y));
        h.y = h2u(__floats2half2_rn(v.z, v.w));
        q[i] = h;
    }
    #pragma unroll
    for (int o = 16; o > 0; o >>= 1) s += __shfl_down_sync(0xffffffffu, s, o);
    __shared__ float red[8];
    int lane = threadIdx.x & 31, wid = threadIdx.x >> 5;
    if (lane == 0) red[wid] = s;
    __syncthreads();
    if (wid == 0) {
        s = (lane < 8) ? red[lane] : 0.f;
        #pragma unroll
        for (int o = 4; o > 0; o >>= 1) s += __shfl_down_sync(0xffffffffu, s, o);
        if (lane == 0) g_dinv[row] = (s > 0.f) ? rsqrtf(s) : 0.f;
    }
}

// ---------------------------------------------------------------------------
// Kernel 1: g_h[k][n] = fp16( dinv[k] * (x[k,:] @ W)[n] )
// ---------------------------------------------------------------------------
__global__ void __launch_bounds__(256) proj_kernel(const float* __restrict__ x,
                                                   const float* __restrict__ w) {
    __shared__ float xs[32][D];
    int row0 = blockIdx.x * 32;
    int tid = threadIdx.x;
    for (int i = tid; i < 32 * D; i += 256)
        xs[i / D][i % D] = x[(size_t)(row0 + i / D) * D + (i % D)];
    __syncthreads();

    int d = tid & 127;
    int half_ = tid >> 7;
    float acc[16];
    #pragma unroll
    for (int r = 0; r < 16; r++) acc[r] = 0.f;

    for (int k = 0; k < D; k++) {
        float wv = w[k * D + d];
        #pragma unroll
        for (int r = 0; r < 16; r++)
            acc[r] += xs[half_ * 16 + r][k] * wv;
    }
    #pragma unroll
    for (int r = 0; r < 16; r++) {
        int row = row0 + half_ * 16 + r;
        g_h[(size_t)row * D + d] = __float2half(acc[r] * g_dinv[row]);
    }
}

// ---------------------------------------------------------------------------
// Kernel 2: fp16 GEMM partials via mma.sync (fp32 accum), split-K=2.
// grid (128,2): CTA = M64 x N128 x K4096. 256 threads, 8 warps 2(M)x4(N),
// warp tile 32x32, occ 2. 4-slot static ring, round-9 pipeline semantics.
// ---------------------------------------------------------------------------
__global__ void __launch_bounds__(256, 2) gemm_kernel() {
    extern __shared__ __align__(16) unsigned char smbuf[];
    const uint32_t sm = smem_u32(smbuf);

    const int tid = threadIdx.x;
    const int lane = tid & 31;
    const int wid = tid >> 5;
    const int wr = wid & 1;          // warp row  (32 rows)
    const int wc = wid >> 1;         // warp col  (32 cols)
    const int row0 = blockIdx.x * MT;
    const int kb0 = blockIdx.y * KSPLIT;

    // ---- A loader: 2 cp.async16 per thread per stage (64 rows x 64 k) ----
    const int ar0 = tid >> 3;                // chunk tid: row 0..31
    const int ar1 = (tid + 256) >> 3;        // row 32..63
    const int ak8 = (tid & 7) * 8;
    const uint32_t a_off0 = (((uint32_t)ar0 * KCG + ak8) * 2) ^ ((uint32_t)(ar0 & 7) << 4);
    const uint32_t a_off1 = (((uint32_t)ar1 * KCG + ak8) * 2) ^ ((uint32_t)(ar1 & 7) << 4);
    const __half* asrc0 = g_ah + (size_t)(row0 + ar0) * N_NODES + kb0 + ak8;
    const __half* asrc1 = g_ah + (size_t)(row0 + ar1) * N_NODES + kb0 + ak8;

    // ---- B loader: 4 cp.async16 per thread per stage (64 k x 128 n) ----
    const int bk = tid >> 2;
    const int bnc0 = (tid & 3) * 4;
    uint32_t b_off[4];
    #pragma unroll
    for (int j = 0; j < 4; j++)
        b_off[j] = (((uint32_t)bk * D + (bnc0 + j) * 8) * 2) ^ ((uint32_t)(bk & 7) << 4);
    const __half* bsrc = g_h + (size_t)(kb0 + bk) * D + bnc0 * 8;

    // ---- mma fragment addressing ----
    const uint32_t axor_f = (uint32_t)((lane & 15) & 7) << 4;
    const uint32_t aoff_m0 = (((uint32_t)(wr * 32 + (lane & 15)) * KCG + (lane >> 4) * 8) * 2);
    const uint32_t aoff_m1 = aoff_m0 + 16u * KCG * 2;   // +16 rows
    const int brow_l = (lane & 7) + ((lane >> 3) & 1) * 8;
    const uint32_t bxor_f = (uint32_t)(lane & 7) << 4;
    const uint32_t boff_l = ((uint32_t)brow_l * D + wc * 32 + (lane >> 4) * 8) * 2;
    const int n0w = wc * 32;

    float c[8][4];
    #pragma unroll
    for (int j = 0; j < 8; j++)
        #pragma unroll
        for (int q = 0; q < 4; q++) c[j][q] = 0.f;

    #define ISSUE_STAGE(base, p)                                                   \
        do {                                                                       \
            cp_async16((base) + a_off0, asrc0 + (size_t)(p) * KCG);                \
            cp_async16((base) + a_off1, asrc1 + (size_t)(p) * KCG);                \
            const __half* _bp = bsrc + (size_t)(p) * KCG * D;                      \
            cp_async16((base) + A_TILE_B + b_off[0], _bp);                         \
            cp_async16((base) + A_TILE_B + b_off[1], _bp + 8);                     \
            cp_async16((base) + A_TILE_B + b_off[2], _bp + 16);                    \
            cp_async16((base) + A_TILE_B + b_off[3], _bp + 24);                    \
        } while (0)

    #define COMPUTE_STAGE(sA, sB)                                                  \
        do {                                                                       \
            _Pragma("unroll")                                                      \
            for (int s16 = 0; s16 < 4; s16++) {                                    \
                uint32_t ra0[4], ra1[4];                                           \
                ldsm_x4(ra0, (sA) + ((aoff_m0 + 32u * s16) ^ axor_f));             \
                ldsm_x4(ra1, (sA) + ((aoff_m1 + 32u * s16) ^ axor_f));             \
                uint32_t rb0[4], rb1[4];                                           \
                ldsm_x4_t(rb0, (sB) + ((boff_l + 4096u * s16) ^ bxor_f));          \
                ldsm_x4_t(rb1, (sB) + ((boff_l + 4096u * s16 + 32u) ^ bxor_f));    \
                mma16816(c[0], ra0, rb0[0], rb0[1]);                               \
                mma16816(c[1], ra0, rb0[2], rb0[3]);                               \
                mma16816(c[2], ra0, rb1[0], rb1[1]);                               \
                mma16816(c[3], ra0, rb1[2], rb1[3]);                               \
                mma16816(c[4], ra1, rb0[0], rb0[1]);                               \
                mma16816(c[5], ra1, rb0[2], rb0[3]);                               \
                mma16816(c[6], ra1, rb1[0], rb1[1]);                               \
                mma16816(c[7], ra1, rb1[2], rb1[3]);                               \
            }                                                                      \
        } while (0)

    #define STEP(slot_issue, slot_comp, p_issue)                                   \
        do {                                                                       \
            cp_wait2();                                                            \
            __syncthreads();                                                       \
            if ((p_issue) < NITER_S) ISSUE_STAGE(slot_issue, p_issue);             \
            cp_commit();                                                           \
            COMPUTE_STAGE(slot_comp, (slot_comp) + A_TILE_B);                      \
        } while (0)

    const uint32_t s0 = sm;
    const uint32_t s1 = sm + STAGE_B;
    const uint32_t s2 = sm + 2 * STAGE_B;
    const uint32_t s3 = sm + 3 * STAGE_B;

    ISSUE_STAGE(s0, 0); cp_commit();
    ISSUE_STAGE(s1, 1); cp_commit();
    ISSUE_STAGE(s2, 2); cp_commit();

    for (int j = 0; j < NITER_S / 4; j++) {
        const int p = 4 * j;
        STEP(s3, s0, p + 3);
        STEP(s0, s1, p + 4);
        STEP(s1, s2, p + 5);
        STEP(s2, s3, p + 6);
    }

    // ---- epilogue: raw fp32 partials -> g_part[by] ----
    float* part = g_part + (size_t)blockIdx.y * N_NODES * D;
    const int grp = lane >> 2, tid4 = lane & 3;
    #pragma unroll
    for (int mf = 0; mf < 2; mf++) {
        const int r1 = row0 + wr * 32 + mf * 16 + grp;
        const int r2 = r1 + 8;
        #pragma unroll
        for (int j = 0; j < 4; j++) {
            int col = n0w + j * 8 + tid4 * 2;
            float2 o1, o2;
            o1.x = c[mf * 4 + j][0];
            o1.y = c[mf * 4 + j][1];
            o2.x = c[mf * 4 + j][2];
            o2.y = c[mf * 4 + j][3];
            *reinterpret_cast<float2*>(part + (size_t)r1 * D + col) = o1;
            *reinterpret_cast<float2*>(part + (size_t)r2 * D + col) = o2;
        }
    }
    #undef ISSUE_STAGE
    #undef COMPUTE_STAGE
    #undef STEP
}

// ---------------------------------------------------------------------------
// Kernel 3: out = dinv * (P0 + P1) + bias
// ---------------------------------------------------------------------------
__global__ void __launch_bounds__(256) combine_kernel(const float* __restrict__ bias,
                                                      float* __restrict__ out) {
    int idx = blockIdx.x * 256 + threadIdx.x;      // over 8192*32 float4s
    int row = idx >> 5;
    int c4 = idx & 31;
    const float4* p0 = reinterpret_cast<const float4*>(g_part);
    const float4* p1 = reinterpret_cast<const float4*>(g_part + (size_t)N_NODES * D);
    float4 a = p0[idx], b = p1[idx];
    float di = g_dinv[row];
    float4 bv = reinterpret_cast<const float4*>(bias)[c4];
    float4 o;
    o.x = fmaf(a.x + b.x, di, bv.x);
    o.y = fmaf(a.y + b.y, di, bv.y);
    o.z = fmaf(a.z + b.z, di, bv.z);
    o.w = fmaf(a.w + b.w, di, bv.w);
    reinterpret_cast<float4*>(out)[idx] = o;
}

// ---------------------------------------------------------------------------
extern "C" void kernel_launch(void* const* d_in, const int* in_sizes, int n_in,
                              void* d_out, int out_size) {
    const float* x = nullptr;
    const float* adj = nullptr;
    const float* weight = nullptr;
    const float* bias = nullptr;
    for (int i = 0; i < n_in; i++) {
        long long sz = in_sizes[i];
        if (sz == (long long)N_NODES * N_NODES) adj = (const float*)d_in[i];
        else if (sz == (long long)N_NODES * D)  x = (const float*)d_in[i];
        else if (sz == (long long)D * D)        weight = (const float*)d_in[i];
        else if (sz == D)                       bias = (const float*)d_in[i];
    }
    float* out = (float*)d_out;

    cudaFuncSetAttribute(gemm_kernel,
                         cudaFuncAttributeMaxDynamicSharedMemorySize, SMEM_BYTES);

    rowsum_cvt_kernel<<<N_NODES, 256>>>(adj);
    proj_kernel<<<N_NODES / 32, 256>>>(x, weight);
    gemm_kernel<<<dim3(N_NODES / MT, NSPLIT), 256, SMEM_BYTES>>>();
    combine_kernel<<<N_NODES * D / 4 / 256, 256>>>(bias, out);
}